// round 1
// baseline (speedup 1.0000x reference)
#include <cuda_runtime.h>
#include <cstdint>

// ---------------------------------------------------------------------------
// DisentanglementModule loss, closed form.
//
// For each feature matrix x (B x d):
//   D[i,j] = ||x_i - x_j||^2 / d
//   loss_x = sum_{i<j,same}(D - tau)/c_pos + sum_{i<j,diff}(tau - D)/c_neg
// With TAU_POS == TAU_NEG the tau terms cancel exactly, leaving
//   loss_x = S_pos/c_pos - S_neg/c_neg
// where, with per-group column sums s_g[c] and per-group sum-of-squares q_g:
//   S_pos = sum_g (n_g * q_g - ||m_g||^2) / d
//   S_all = (B * Q - ||M||^2) / d ,  S_neg = S_all - S_pos
// All statistics are column-separable -> single streaming pass.
// ---------------------------------------------------------------------------

#define NB      4096
#define NCHUNK  64          // row chunks
#define RPC     64          // rows per chunk  (NCHUNK * RPC == NB)
#define NTILE   5           // column tiles (2x rep, act0, act1, act2)
#define TSLOT   512         // column slots per tile (128 thr * float4)
#define SLOTS   (NTILE * TSLOT)   // 2560
#define NSB     (4 * NTILE)       // 20 k2a blocks

// Scratch (graph-capturable: no allocations). Every element is rewritten on
// every launch, so no zero-init is required across graph replays.
__device__ __align__(16) float g_Spart[NCHUNK * 4 * SLOTS]; // per-chunk per-group column sums
__device__ float  g_Tblk[NTILE * NCHUNK * 4];               // per-block per-group sum-of-squares
__device__ double g_SBlk[NSB * 5];                          // per-k2a-block {msq_g x4, Msq}
__device__ int    g_grp[NB];                                // decoded group ids

// ---------------------------------------------------------------------------
// K0: decode noise_levels. Handles both int64 and int32 storage:
// values are in [0,3], so if the buffer is int64 (little-endian), every odd
// 32-bit word of the first NB words is 0 and every even word is <= 3.
// ---------------------------------------------------------------------------
__global__ void k0_groups(const int* __restrict__ nl32) {
    __shared__ int flag64;
    const int tid = threadIdx.x;
    if (tid == 0) flag64 = 1;
    __syncthreads();
    int bad = 0;
    for (int i = tid; i < NB / 2; i += blockDim.x) {
        int lo = nl32[2 * i];
        int hi = nl32[2 * i + 1];
        if (hi != 0 || (unsigned)lo > 3u) bad = 1;
    }
    if (bad) atomicExch(&flag64, 0);
    __syncthreads();
    const int is64 = flag64;
    for (int i = tid; i < NB; i += blockDim.x)
        g_grp[i] = is64 ? nl32[2 * i] : nl32[i];
}

// ---------------------------------------------------------------------------
// K1: main streaming pass. grid = (NTILE, NCHUNK), 128 threads.
// Each thread owns 4 consecutive columns (float4) of one tile and walks RPC
// rows, accumulating per-group column sums (s) and sum-of-squares (t).
// The group branch is warp-uniform (same row for all lanes) -> no divergence.
// ---------------------------------------------------------------------------
#define ACC8(S, T, x) do {                              \
    S.x += x.x; S.y += x.y; S.z += x.z; S.w += x.w;     \
    T.x = fmaf(x.x, x.x, T.x); T.y = fmaf(x.y, x.y, T.y); \
    T.z = fmaf(x.z, x.z, T.z); T.w = fmaf(x.w, x.w, T.w); } while (0)

__global__ __launch_bounds__(128) void k1_partial(
    const float* __restrict__ rep, const float* __restrict__ a0,
    const float* __restrict__ a1,  const float* __restrict__ a2)
{
    const int tile = blockIdx.x, chunk = blockIdx.y, tid = threadIdx.x;

    const float* src; int ld, colBase, ncols;
    switch (tile) {
        case 0:  src = rep; ld = 1024; colBase = 0;   ncols = 512; break;
        case 1:  src = rep; ld = 1024; colBase = 512; ncols = 512; break;
        case 2:  src = a0;  ld = 512;  colBase = 0;   ncols = 64;  break;
        case 3:  src = a1;  ld = 512;  colBase = 0;   ncols = 128; break;
        default: src = a2;  ld = 512;  colBase = 0;   ncols = 256; break;
    }

    __shared__ int gsh[RPC];
    const int row0 = chunk * RPC;
    if (tid < RPC) gsh[tid] = g_grp[row0 + tid];
    __syncthreads();

    const int colLocal = tid * 4;
    const float4 z = make_float4(0.f, 0.f, 0.f, 0.f);
    float4 sA = z, sB = z, sC = z, sD = z;
    float4 tA = z, tB = z, tC = z, tD = z;

    if (colLocal < ncols) {
        const float* p = src + (size_t)row0 * ld + colBase + colLocal;
        #pragma unroll 1
        for (int r = 0; r < RPC; r += 8) {
            float4 v[8]; int gg[8];
            #pragma unroll
            for (int u = 0; u < 8; u++) {          // batch loads for MLP
                v[u]  = *reinterpret_cast<const float4*>(p + (size_t)(r + u) * ld);
                gg[u] = gsh[r + u];
            }
            #pragma unroll
            for (int u = 0; u < 8; u++) {
                const float4 x = v[u];
                const int g = gg[u];               // warp-uniform
                if      (g == 0) ACC8(sA, tA, x);
                else if (g == 1) ACC8(sB, tB, x);
                else if (g == 2) ACC8(sC, tC, x);
                else             ACC8(sD, tD, x);
            }
        }
    }

    // Store per-group column-sum partials (inactive threads store zeros so the
    // whole scratch is rewritten deterministically each launch).
    const int slot = tile * TSLOT + colLocal;
    float4* Sp = reinterpret_cast<float4*>(g_Spart);
    Sp[((chunk * 4 + 0) * SLOTS + slot) >> 2] = sA;
    Sp[((chunk * 4 + 1) * SLOTS + slot) >> 2] = sB;
    Sp[((chunk * 4 + 2) * SLOTS + slot) >> 2] = sC;
    Sp[((chunk * 4 + 3) * SLOTS + slot) >> 2] = sD;

    // Block-reduce sum-of-squares per group (4 scalars per block).
    __shared__ float red[128];
    float tg[4] = { tA.x + tA.y + tA.z + tA.w, tB.x + tB.y + tB.z + tB.w,
                    tC.x + tC.y + tC.z + tC.w, tD.x + tD.y + tD.z + tD.w };
    #pragma unroll
    for (int g = 0; g < 4; g++) {
        __syncthreads();
        red[tid] = tg[g];
        __syncthreads();
        for (int off = 64; off > 0; off >>= 1) {
            if (tid < off) red[tid] += red[tid + off];
            __syncthreads();
        }
        if (tid == 0) g_Tblk[(tile * NCHUNK + chunk) * 4 + g] = red[0];
    }
}

// ---------------------------------------------------------------------------
// K2a: reduce chunk partials -> full per-group column sums; square and
// partially reduce into per-matrix {||m_g||^2 x4, ||M||^2}. 20 blocks x 128.
// Each block spans 128 slots, all belonging to one matrix.
// ---------------------------------------------------------------------------
__global__ __launch_bounds__(128) void k2a_colreduce() {
    const int tid  = threadIdx.x;
    const int slot = blockIdx.x * 128 + tid;
    double s0 = 0.0, s1 = 0.0, s2 = 0.0, s3 = 0.0;
    for (int ch = 0; ch < NCHUNK; ch++) {
        const float* base = g_Spart + (size_t)ch * 4 * SLOTS + slot;
        s0 += (double)base[0 * SLOTS];
        s1 += (double)base[1 * SLOTS];
        s2 += (double)base[2 * SLOTS];
        s3 += (double)base[3 * SLOTS];
    }
    const double stot = s0 + s1 + s2 + s3;
    double vals[5] = { s0 * s0, s1 * s1, s2 * s2, s3 * s3, stot * stot };

    __shared__ double dred[128];
    #pragma unroll
    for (int k = 0; k < 5; k++) {
        __syncthreads();
        dred[tid] = vals[k];
        __syncthreads();
        for (int off = 64; off > 0; off >>= 1) {
            if (tid < off) dred[tid] += dred[tid + off];
            __syncthreads();
        }
        if (tid == 0) g_SBlk[blockIdx.x * 5 + k] = dred[0];
    }
}

// ---------------------------------------------------------------------------
// K2b: finalize. 1 block x 256. Group counts, q[m][g], combine, write loss.
// All reductions fixed-order -> bitwise deterministic.
// ---------------------------------------------------------------------------
__global__ __launch_bounds__(256) void k2b_final(float* __restrict__ out, int out_size) {
    const int tid = threadIdx.x;

    // --- group counts ---
    int c[4] = {0, 0, 0, 0};
    for (int i = tid; i < NB; i += 256) {
        const int g = g_grp[i];
        c[0] += (g == 0); c[1] += (g == 1); c[2] += (g == 2); c[3] += (g == 3);
    }
    __shared__ int ired[256];
    __shared__ int cnt_sh[4];
    #pragma unroll
    for (int g = 0; g < 4; g++) {
        __syncthreads();
        ired[tid] = c[g];
        __syncthreads();
        for (int off = 128; off > 0; off >>= 1) {
            if (tid < off) ired[tid] += ired[tid + off];
            __syncthreads();
        }
        if (tid == 0) cnt_sh[g] = ired[0];
    }

    // --- q[m][g] from Tblk ---
    double q[16];
    #pragma unroll
    for (int k = 0; k < 16; k++) q[k] = 0.0;
    for (int b = tid; b < NTILE * NCHUNK; b += 256) {
        const int t = b / NCHUNK;
        const int m = (t <= 1) ? 0 : (t - 1);
        #pragma unroll
        for (int g = 0; g < 4; g++)
            q[m * 4 + g] += (double)g_Tblk[b * 4 + g];
    }
    __shared__ double dsh[256];
    __shared__ double q_sh[16];
    #pragma unroll
    for (int k = 0; k < 16; k++) {
        __syncthreads();
        dsh[tid] = q[k];
        __syncthreads();
        for (int off = 128; off > 0; off >>= 1) {
            if (tid < off) dsh[tid] += dsh[tid + off];
            __syncthreads();
        }
        if (tid == 0) q_sh[k] = dsh[0];
    }
    __syncthreads();

    if (tid == 0) {
        double msq[16], Msq[4];
        #pragma unroll
        for (int k = 0; k < 16; k++) msq[k] = 0.0;
        #pragma unroll
        for (int m = 0; m < 4; m++) Msq[m] = 0.0;
        for (int b = 0; b < NSB; b++) {
            const int m = (b < 8) ? 0 : (b < 12) ? 1 : (b < 16) ? 2 : 3;
            #pragma unroll
            for (int g = 0; g < 4; g++) msq[m * 4 + g] += g_SBlk[b * 5 + g];
            Msq[m] += g_SBlk[b * 5 + 4];
        }

        double n[4]; double cpos = 0.0;
        #pragma unroll
        for (int g = 0; g < 4; g++) {
            n[g] = (double)cnt_sh[g];
            cpos += 0.5 * n[g] * (n[g] - 1.0);
        }
        const double Bv   = (double)NB;
        const double cneg = 0.5 * Bv * (Bv - 1.0) - cpos;
        const double dm[4] = {1024.0, 64.0, 128.0, 256.0};

        double loss[4];
        #pragma unroll
        for (int m = 0; m < 4; m++) {
            double Spos = 0.0, Q = 0.0;
            #pragma unroll
            for (int g = 0; g < 4; g++) {
                Spos += n[g] * q_sh[m * 4 + g] - msq[m * 4 + g];
                Q    += q_sh[m * 4 + g];
            }
            Spos /= dm[m];
            const double Sall = (Bv * Q - Msq[m]) / dm[m];
            const double Sneg = Sall - Spos;
            loss[m] = Spos / cpos - Sneg / cneg;
        }
        const double latent = (loss[1] + loss[2] + loss[3]) / 3.0;
        out[0] = (float)(0.5 * latent + 0.5 * loss[0]);  // W = 0.5
    }
    for (int i = 1 + tid; i < out_size; i += 256) out[i] = 0.0f;
}

// ---------------------------------------------------------------------------
extern "C" void kernel_launch(void* const* d_in, const int* in_sizes, int n_in,
                              void* d_out, int out_size) {
    const float* rep = (const float*)d_in[0];
    const float* a0  = (const float*)d_in[1];
    const float* a1  = (const float*)d_in[2];
    const float* a2  = (const float*)d_in[3];
    const int*   nl  = (const int*)d_in[4];   // int32 view; k0 detects int64

    k0_groups<<<1, 1024>>>(nl);
    dim3 g1(NTILE, NCHUNK);
    k1_partial<<<g1, 128>>>(rep, a0, a1, a2);
    k2a_colreduce<<<NSB, 128>>>();
    k2b_final<<<1, 256>>>((float*)d_out, out_size);
}

// round 4
// speedup vs baseline: 1.3384x; 1.3384x over previous
#include <cuda_runtime.h>
#include <cstdint>

// ---------------------------------------------------------------------------
// DisentanglementModule loss, closed form (TAU_POS == TAU_NEG => tau cancels):
//   loss_x = S_pos/c_pos - S_neg/c_neg
//   S_pos  = sum_g (n_g * q_g - ||m_g||^2) / d
//   S_all  = (B * Q - ||M||^2) / d ,  S_neg = S_all - S_pos
// m_g[c] (per-group column sums) and q_g (per-group sum of squares) are
// column-separable -> one streaming pass + tiny reductions.
//
// 3 plain kernels (no device-side tickets/atomics/fences):
//   kA: stream 24MB of features into per-chunk per-group partials
//   kB: reduce chunk partials -> per-block {||m_g||^2, ||M||^2}
//   kC: 1 block, parallel-staged finalize -> loss scalar
// ---------------------------------------------------------------------------

#define NB      4096
#define NCHUNK  32                 // row chunks
#define RPC     128                // rows per chunk (NCHUNK*RPC == NB)
#define NTILE   5                  // column tiles (2x rep, act0, act1, act2)
#define TSLOT   512                // column slots per tile (128 thr * float4)
#define SLOTS   (NTILE * TSLOT)    // 2560
#define NKB     20                 // kB blocks (SLOTS / 128)
#define FULL    0xFFFFFFFFu

// Scratch: every element rewritten on every launch -> graph-replay safe.
__device__ __align__(16) float g_Spart[NCHUNK * 4 * SLOTS]; // [ch][g][slot]
__device__ float  g_Qblk[NTILE * NCHUNK * 4];               // per-kA-block q_g
__device__ double g_SBlk[NKB * 5];                          // per-kB-block {msq_g x4, Msq}

// Decode helper: values are in [0,3]; if buffer is int64 (LE), odd 32-bit
// words are all 0 and even words <= 3. Whole-array vote via syncthreads_count.
__device__ __forceinline__ int detect_int64(const int* __restrict__ nl, int tid, int nthr) {
    int bad = 0;
    for (int i = tid; i < NB / 2; i += nthr) {
        const int lo = nl[2 * i], hi = nl[2 * i + 1];
        if (hi != 0 || (unsigned)lo > 3u) bad = 1;
    }
    return __syncthreads_count(bad) == 0;   // all threads agree
}

// ---------------------------------------------------------------------------
// kA: streaming pass. grid=(NTILE, NCHUNK), 128 threads. Thread owns 4 cols.
// ---------------------------------------------------------------------------
#define ACC8(S, T, x) do {                                   \
    S.x += x.x; S.y += x.y; S.z += x.z; S.w += x.w;          \
    T.x = fmaf(x.x, x.x, T.x); T.y = fmaf(x.y, x.y, T.y);    \
    T.z = fmaf(x.z, x.z, T.z); T.w = fmaf(x.w, x.w, T.w); } while (0)

__global__ __launch_bounds__(128) void kA_partial(
    const float* __restrict__ rep, const float* __restrict__ a0,
    const float* __restrict__ a1,  const float* __restrict__ a2,
    const int* __restrict__ nl)
{
    const int tile = blockIdx.x, chunk = blockIdx.y, tid = threadIdx.x;

    const float* src; int ld, colBase, ncols;
    switch (tile) {
        case 0:  src = rep; ld = 1024; colBase = 0;   ncols = 512; break;
        case 1:  src = rep; ld = 1024; colBase = 512; ncols = 512; break;
        case 2:  src = a0;  ld = 512;  colBase = 0;   ncols = 64;  break;
        case 3:  src = a1;  ld = 512;  colBase = 0;   ncols = 128; break;
        default: src = a2;  ld = 512;  colBase = 0;   ncols = 256; break;
    }

    const int is64 = detect_int64(nl, tid, 128);
    __shared__ int gsh[RPC];
    const int row0 = chunk * RPC;
    gsh[tid] = is64 ? nl[2 * (row0 + tid)] : nl[row0 + tid];   // RPC==128==blockDim
    __syncthreads();

    const int colLocal = tid * 4;
    const float4 z = make_float4(0.f, 0.f, 0.f, 0.f);
    float4 sA = z, sB = z, sC = z, sD = z;
    float4 tA = z, tB = z, tC = z, tD = z;

    if (colLocal < ncols) {
        const float* p = src + (size_t)row0 * ld + colBase + colLocal;
        #pragma unroll 1
        for (int r = 0; r < RPC; r += 8) {
            float4 v[8]; int gg[8];
            #pragma unroll
            for (int u = 0; u < 8; u++) {                       // batch for MLP
                v[u]  = *reinterpret_cast<const float4*>(p + (size_t)(r + u) * ld);
                gg[u] = gsh[r + u];
            }
            #pragma unroll
            for (int u = 0; u < 8; u++) {
                const float4 x = v[u];
                const int g = gg[u];                            // warp-uniform
                if      (g == 0) ACC8(sA, tA, x);
                else if (g == 1) ACC8(sB, tB, x);
                else if (g == 2) ACC8(sC, tC, x);
                else             ACC8(sD, tD, x);
            }
        }
    }

    // Per-group column-sum partials (idle threads store zeros: scratch fully
    // rewritten each launch).
    const int slot = tile * TSLOT + colLocal;
    float4* Sp = reinterpret_cast<float4*>(g_Spart);
    Sp[((chunk * 4 + 0) * SLOTS + slot) >> 2] = sA;
    Sp[((chunk * 4 + 1) * SLOTS + slot) >> 2] = sB;
    Sp[((chunk * 4 + 2) * SLOTS + slot) >> 2] = sC;
    Sp[((chunk * 4 + 3) * SLOTS + slot) >> 2] = sD;

    // Block-reduce q_g (sum of squares) via warp shuffles.
    const int lane = tid & 31, warp = tid >> 5;
    float tg[4] = { tA.x + tA.y + tA.z + tA.w, tB.x + tB.y + tB.z + tB.w,
                    tC.x + tC.y + tC.z + tC.w, tD.x + tD.y + tD.z + tD.w };
    __shared__ float wsum[4][4];
    #pragma unroll
    for (int g = 0; g < 4; g++) {
        float v = tg[g];
        #pragma unroll
        for (int off = 16; off > 0; off >>= 1) v += __shfl_down_sync(FULL, v, off);
        if (lane == 0) wsum[g][warp] = v;
    }
    __syncthreads();
    if (tid < 4)
        g_Qblk[(tile * NCHUNK + chunk) * 4 + tid] =
            wsum[tid][0] + wsum[tid][1] + wsum[tid][2] + wsum[tid][3];
}

// ---------------------------------------------------------------------------
// kB: reduce chunk partials -> per-block {||m_g||^2 partial x4, ||M||^2 partial}.
// Block b covers slots [b*128,(b+1)*128).
// ---------------------------------------------------------------------------
__global__ __launch_bounds__(128) void kB_reduce() {
    const int tid = threadIdx.x, b = blockIdx.x;
    const int lane = tid & 31, warp = tid >> 5;
    const int slot = b * 128 + tid;

    // Column sums over chunks (float accumulation: 32 addends; error << fp32
    // noise already present in kA). Two-way split for ILP.
    float f0a = 0.f, f1a = 0.f, f2a = 0.f, f3a = 0.f;
    float f0b = 0.f, f1b = 0.f, f2b = 0.f, f3b = 0.f;
    #pragma unroll 4
    for (int ch = 0; ch < NCHUNK; ch += 2) {
        const float* pa = g_Spart + (size_t)(ch + 0) * 4 * SLOTS + slot;
        const float* pb = g_Spart + (size_t)(ch + 1) * 4 * SLOTS + slot;
        f0a += pa[0 * SLOTS]; f1a += pa[1 * SLOTS]; f2a += pa[2 * SLOTS]; f3a += pa[3 * SLOTS];
        f0b += pb[0 * SLOTS]; f1b += pb[1 * SLOTS]; f2b += pb[2 * SLOTS]; f3b += pb[3 * SLOTS];
    }
    const double s0 = (double)(f0a + f0b), s1 = (double)(f1a + f1b);
    const double s2 = (double)(f2a + f2b), s3 = (double)(f3a + f3b);
    const double st = s0 + s1 + s2 + s3;
    double vals[5] = { s0 * s0, s1 * s1, s2 * s2, s3 * s3, st * st };

    // Reduce 5 doubles across the block via shuffles.
    __shared__ double wsumd[5][4];
    #pragma unroll
    for (int k = 0; k < 5; k++) {
        double v = vals[k];
        #pragma unroll
        for (int off = 16; off > 0; off >>= 1) v += __shfl_down_sync(FULL, v, off);
        if (lane == 0) wsumd[k][warp] = v;
    }
    __syncthreads();
    if (tid < 5)
        g_SBlk[b * 5 + tid] = wsumd[tid][0] + wsumd[tid][1] + wsumd[tid][2] + wsumd[tid][3];
}

// ---------------------------------------------------------------------------
// kC: finalize. 1 block x 128. All global reads are cooperative/coalesced
// (one latency exposure each), then tiny shared-memory math on thread 0.
// ---------------------------------------------------------------------------
__global__ __launch_bounds__(128) void kC_final(
    const int* __restrict__ nl, float* __restrict__ out, int out_size)
{
    const int tid = threadIdx.x;
    const int lane = tid & 31, warp = tid >> 5;

    // Stage g_SBlk (100 doubles) into shared: one coalesced wave.
    __shared__ double sb[NKB * 5];
    if (tid < NKB * 5) sb[tid] = g_SBlk[tid];

    // Group counts (decode noise_levels locally).
    const int is64 = detect_int64(nl, tid, 128);   // has a barrier inside
    int c[4] = {0, 0, 0, 0};
    for (int i = tid; i < NB; i += 128) {
        const int v = (is64 ? nl[2 * i] : nl[i]) & 3;
        c[v]++;
    }
    __shared__ int cw[4][4];
    __shared__ int cnt_sh[4];
    #pragma unroll
    for (int g = 0; g < 4; g++) {
        int v = c[g];
        #pragma unroll
        for (int off = 16; off > 0; off >>= 1) v += __shfl_down_sync(FULL, v, off);
        if (lane == 0) cw[g][warp] = v;
    }
    __syncthreads();
    if (tid < 4) cnt_sh[tid] = cw[tid][0] + cw[tid][1] + cw[tid][2] + cw[tid][3];

    // q[m][g] from g_Qblk (640 floats). kA block id = tile*NCHUNK+chunk:
    // m0 <- ids [0,64); m1 <- [64,96); m2 <- [96,128); m3 <- [128,160).
    const int k = tid & 15, rep = tid >> 4;          // 16 accums x 8 reps
    const int m = k >> 2, g = k & 3;
    const int start = (m == 0) ? 0 : 32 * (m + 1);
    const int count = (m == 0) ? 2 * NCHUNK : NCHUNK;
    float qv = 0.f;
    for (int j = rep; j < count; j += 8) qv += g_Qblk[(start + j) * 4 + g];
    __shared__ float qpart[128];
    __shared__ double q_sh[16];
    qpart[tid] = qv;
    __syncthreads();
    if (tid < 16) {
        double q = 0.0;
        #pragma unroll
        for (int r = 0; r < 8; r++) q += (double)qpart[tid + 16 * r];
        q_sh[tid] = q;
    }
    __syncthreads();

    if (tid == 0) {
        double msq[16], Msq[4];
        #pragma unroll
        for (int k2 = 0; k2 < 16; k2++) msq[k2] = 0.0;
        #pragma unroll
        for (int m2 = 0; m2 < 4; m2++) Msq[m2] = 0.0;
        #pragma unroll
        for (int bb = 0; bb < NKB; bb++) {           // shared-memory walk (fast)
            const int mm = (bb < 8) ? 0 : (bb < 12) ? 1 : (bb < 16) ? 2 : 3;
            #pragma unroll
            for (int g2 = 0; g2 < 4; g2++) msq[mm * 4 + g2] += sb[bb * 5 + g2];
            Msq[mm] += sb[bb * 5 + 4];
        }

        double n[4], cpos = 0.0;
        #pragma unroll
        for (int g2 = 0; g2 < 4; g2++) {
            n[g2] = (double)cnt_sh[g2];
            cpos += 0.5 * n[g2] * (n[g2] - 1.0);
        }
        const double Bv = (double)NB;
        const double cneg = 0.5 * Bv * (Bv - 1.0) - cpos;
        const double icp = 1.0 / cpos, icn = 1.0 / cneg;      // only 2 divides
        const double idm[4] = {1.0/1024.0, 1.0/64.0, 1.0/128.0, 1.0/256.0}; // exact

        double loss[4];
        #pragma unroll
        for (int m2 = 0; m2 < 4; m2++) {
            double Spos = 0.0, Q = 0.0;
            #pragma unroll
            for (int g2 = 0; g2 < 4; g2++) {
                Spos += n[g2] * q_sh[m2 * 4 + g2] - msq[m2 * 4 + g2];
                Q    += q_sh[m2 * 4 + g2];
            }
            Spos *= idm[m2];
            const double Sall = (Bv * Q - Msq[m2]) * idm[m2];
            const double Sneg = Sall - Spos;
            loss[m2] = Spos * icp - Sneg * icn;
        }
        const double latent = (loss[1] + loss[2] + loss[3]) * (1.0 / 3.0);
        out[0] = (float)(0.5 * latent + 0.5 * loss[0]);       // W = 0.5
    }
    for (int i = 1 + tid; i < out_size; i += 128) out[i] = 0.0f;
}

// ---------------------------------------------------------------------------
extern "C" void kernel_launch(void* const* d_in, const int* in_sizes, int n_in,
                              void* d_out, int out_size) {
    const float* rep = (const float*)d_in[0];
    const float* a0  = (const float*)d_in[1];
    const float* a1  = (const float*)d_in[2];
    const float* a2  = (const float*)d_in[3];
    const int*   nl  = (const int*)d_in[4];   // int32 view; int64 detected on device

    dim3 gA(NTILE, NCHUNK);
    kA_partial<<<gA, 128>>>(rep, a0, a1, a2, nl);
    kB_reduce<<<NKB, 128>>>();
    kC_final<<<1, 128>>>(nl, (float*)d_out, out_size);
}

// round 6
// speedup vs baseline: 1.4124x; 1.0553x over previous
#include <cuda_runtime.h>
#include <cstdint>

// ---------------------------------------------------------------------------
// DisentanglementModule loss, closed form (TAU_POS == TAU_NEG => tau cancels):
//   loss_x = S_pos/c_pos - S_neg/c_neg
//   S_pos  = sum_g (n_g * q_g - ||m_g||^2) / d
//   S_all  = (B * Q - ||M||^2) / d ,  S_neg = S_all - S_pos
// Everything is column-separable: per-column per-group sums (m) and
// sums-of-squares (q). One streaming pass + tiny reductions.
//
// Flattened column space: 384 float4 "slots", warp-aligned per matrix:
//   slots [0,256)    rep   (1024 cols)            warps 0-7 (of 3x128 blocks)
//   slots [256,272)  act0  (64 cols); [272,288) idle pad     warp 8
//   slots [288,320)  act1  (128 cols)                        warp 9
//   slots [320,384)  act2  (256 cols)                        warps 10-11
// kA: grid (3, NCHUNK) streams features -> per-chunk per-group slot partials
// kB: grid (3, 8) sums 16 chunks each -> 8 partial planes
// kC: 1 block x 384 finalizes (warp-uniform matrix mapping).
// ---------------------------------------------------------------------------

#define NB      4096
#define NCHUNK  128
#define RPC     32                  // rows per chunk (NCHUNK*RPC == NB)
#define NSLOT   384
#define KB_CH   16                  // chunks per kB block
#define KB_Y    8                   // NCHUNK / KB_CH
#define FULL    0xFFFFFFFFu

// Scratch: every element rewritten each launch -> graph-replay safe.
__device__ __align__(16) float4 g_Spart[NCHUNK * 4 * NSLOT]; // 3.1MB col sums
__device__ float  g_Qpart[NCHUNK * 4 * NSLOT];               // 786KB col sumsq
__device__ __align__(16) float4 g_S2[KB_Y * 4 * NSLOT];      // 196KB
__device__ float  g_Q2[KB_Y * 4 * NSLOT];                    // 49KB

#define F4Z make_float4(0.f, 0.f, 0.f, 0.f)
__device__ __forceinline__ void f4add(float4& a, const float4 b) {
    a.x += b.x; a.y += b.y; a.z += b.z; a.w += b.w;
}

// int64-vs-int32 detection: values in [0,3]; if int64 (LE), odd words are 0
// and even words <= 3. Vote over first 1024 pairs via __syncthreads_count.
__device__ __forceinline__ int detect_int64(const int* __restrict__ nl, int tid, int nthr) {
    int bad = 0;
    for (int i = tid; i < 1024; i += nthr) {
        const int lo = nl[2 * i], hi = nl[2 * i + 1];
        if (hi != 0 || (unsigned)lo > 3u) bad = 1;
    }
    return __syncthreads_count(bad) == 0;
}

// ---------------------------------------------------------------------------
// kA: streaming pass. grid=(3, NCHUNK), 128 threads; thread = one slot.
// ---------------------------------------------------------------------------
#define ACC8(S, T, x) do {                                   \
    S.x += x.x; S.y += x.y; S.z += x.z; S.w += x.w;          \
    T.x = fmaf(x.x, x.x, T.x); T.y = fmaf(x.y, x.y, T.y);    \
    T.z = fmaf(x.z, x.z, T.z); T.w = fmaf(x.w, x.w, T.w); } while (0)

__global__ __launch_bounds__(128) void kA_partial(
    const float* __restrict__ rep, const float* __restrict__ a0,
    const float* __restrict__ a1,  const float* __restrict__ a2,
    const int* __restrict__ nl)
{
    const int tid   = threadIdx.x;
    const int slot  = blockIdx.x * 128 + tid;
    const int chunk = blockIdx.y;
    const int row0  = chunk * RPC;

    const int is64 = detect_int64(nl, tid, 128);     // barrier inside
    __shared__ int gsh[RPC];
    if (tid < RPC)
        gsh[tid] = (is64 ? nl[2 * (row0 + tid)] : nl[row0 + tid]) & 3;
    __syncthreads();

    // Slot -> (src, ld, col). FIX vs R5: act2 owns slots [320,384) fully
    // (64 slots = 256 cols); the only idle slots are the act0 pad [272,288).
    const float* src; int ld, col, active = 1;
    if (slot < 256)      { src = rep; ld = 1024; col = slot * 4; }
    else if (slot < 272) { src = a0;  ld = 512;  col = (slot - 256) * 4; }
    else if (slot < 288) { src = a0;  ld = 512;  col = 0; active = 0; }  // pad
    else if (slot < 320) { src = a1;  ld = 512;  col = (slot - 288) * 4; }
    else                 { src = a2;  ld = 512;  col = (slot - 320) * 4; }

    float4 sA = F4Z, sB = F4Z, sC = F4Z, sD = F4Z;
    float4 tA = F4Z, tB = F4Z, tC = F4Z, tD = F4Z;

    if (active) {
        const float* p = src + (size_t)row0 * ld + col;
        #pragma unroll 1
        for (int r = 0; r < RPC; r += 8) {
            float4 v[8]; int gg[8];
            #pragma unroll
            for (int u = 0; u < 8; u++) {                       // batch for MLP
                v[u]  = *reinterpret_cast<const float4*>(p + (size_t)(r + u) * ld);
                gg[u] = gsh[r + u];
            }
            #pragma unroll
            for (int u = 0; u < 8; u++) {
                const float4 x = v[u];
                const int g = gg[u];                            // warp-uniform
                if      (g == 0) ACC8(sA, tA, x);
                else if (g == 1) ACC8(sB, tB, x);
                else if (g == 2) ACC8(sC, tC, x);
                else             ACC8(sD, tD, x);
            }
        }
    }

    // Store partials (idle slots store zeros: scratch fully rewritten).
    const int base = (chunk * 4) * NSLOT + slot;
    g_Spart[base + 0 * NSLOT] = sA;
    g_Spart[base + 1 * NSLOT] = sB;
    g_Spart[base + 2 * NSLOT] = sC;
    g_Spart[base + 3 * NSLOT] = sD;
    g_Qpart[base + 0 * NSLOT] = tA.x + tA.y + tA.z + tA.w;
    g_Qpart[base + 1 * NSLOT] = tB.x + tB.y + tB.z + tB.w;
    g_Qpart[base + 2 * NSLOT] = tC.x + tC.y + tC.z + tC.w;
    g_Qpart[base + 3 * NSLOT] = tD.x + tD.y + tD.z + tD.w;
}

// ---------------------------------------------------------------------------
// kB: partial chunk reduction. grid=(3, KB_Y), 128 threads; thread = slot.
// Each block sums KB_CH chunks into one of KB_Y partial planes.
// ---------------------------------------------------------------------------
__global__ __launch_bounds__(128) void kB_reduce() {
    const int tid  = threadIdx.x;
    const int slot = blockIdx.x * 128 + tid;
    const int kk   = blockIdx.y;

    float4 s0 = F4Z, s1 = F4Z, s2 = F4Z, s3 = F4Z;
    float  q0 = 0.f, q1 = 0.f, q2 = 0.f, q3 = 0.f;
    #pragma unroll 4
    for (int c = 0; c < KB_CH; c++) {
        const int b = ((kk * KB_CH + c) * 4) * NSLOT + slot;
        f4add(s0, g_Spart[b + 0 * NSLOT]);
        f4add(s1, g_Spart[b + 1 * NSLOT]);
        f4add(s2, g_Spart[b + 2 * NSLOT]);
        f4add(s3, g_Spart[b + 3 * NSLOT]);
        q0 += g_Qpart[b + 0 * NSLOT];
        q1 += g_Qpart[b + 1 * NSLOT];
        q2 += g_Qpart[b + 2 * NSLOT];
        q3 += g_Qpart[b + 3 * NSLOT];
    }
    const int ob = (kk * 4) * NSLOT + slot;
    g_S2[ob + 0 * NSLOT] = s0;  g_S2[ob + 1 * NSLOT] = s1;
    g_S2[ob + 2 * NSLOT] = s2;  g_S2[ob + 3 * NSLOT] = s3;
    g_Q2[ob + 0 * NSLOT] = q0;  g_Q2[ob + 1 * NSLOT] = q1;
    g_Q2[ob + 2 * NSLOT] = q2;  g_Q2[ob + 3 * NSLOT] = q3;
}

// ---------------------------------------------------------------------------
// kC: finalize. 1 block x 384 (12 warps); thread = slot; warp-uniform matrix.
// Warps 0-7 -> m0(rep,d=1024); warp 8 -> m1(act0,64); warp 9 -> m2(act1,128);
// warps 10-11 -> m3(act2,256). Idle pad slots carry zeros.
// ---------------------------------------------------------------------------
__global__ __launch_bounds__(384) void kC_final(
    const int* __restrict__ nl, float* __restrict__ out, int out_size)
{
    const int tid = threadIdx.x, lane = tid & 31, warp = tid >> 5;

    // Per-slot full column sums / sumsq across the KB_Y planes.
    float4 S[4] = {F4Z, F4Z, F4Z, F4Z};
    float  q[4] = {0.f, 0.f, 0.f, 0.f};
    #pragma unroll
    for (int k = 0; k < KB_Y; k++) {
        const int b = (k * 4) * NSLOT + tid;
        f4add(S[0], g_S2[b + 0 * NSLOT]);
        f4add(S[1], g_S2[b + 1 * NSLOT]);
        f4add(S[2], g_S2[b + 2 * NSLOT]);
        f4add(S[3], g_S2[b + 3 * NSLOT]);
        q[0] += g_Q2[b + 0 * NSLOT];
        q[1] += g_Q2[b + 1 * NSLOT];
        q[2] += g_Q2[b + 2 * NSLOT];
        q[3] += g_Q2[b + 3 * NSLOT];
    }

    // 9 per-slot doubles: msq_g (4), q_g (4), Msq (1).
    double v[9];
    float4 st = F4Z;
    #pragma unroll
    for (int g = 0; g < 4; g++) {
        v[g] = (double)S[g].x * S[g].x + (double)S[g].y * S[g].y
             + (double)S[g].z * S[g].z + (double)S[g].w * S[g].w;
        v[4 + g] = (double)q[g];
        f4add(st, S[g]);
    }
    v[8] = (double)st.x * st.x + (double)st.y * st.y
         + (double)st.z * st.z + (double)st.w * st.w;

    __shared__ double wr[12][9];
    #pragma unroll
    for (int k = 0; k < 9; k++) {
        double x = v[k];
        #pragma unroll
        for (int off = 16; off > 0; off >>= 1) x += __shfl_down_sync(FULL, x, off);
        if (lane == 0) wr[warp][k] = x;
    }

    // Group counts (detect + decode nl). detect has a barrier inside,
    // ordering wr writes before later reads.
    const int is64 = detect_int64(nl, tid, 384);
    int c[4] = {0, 0, 0, 0};
    for (int i = tid; i < NB; i += 384) {
        const int g = (is64 ? nl[2 * i] : nl[i]) & 3;
        c[g]++;
    }
    __shared__ int cw[4][12];
    __shared__ int cnt_sh[4];
    #pragma unroll
    for (int g = 0; g < 4; g++) {
        int x = c[g];
        #pragma unroll
        for (int off = 16; off > 0; off >>= 1) x += __shfl_down_sync(FULL, x, off);
        if (lane == 0) cw[g][warp] = x;
    }
    __syncthreads();
    if (tid < 4) {
        int t = 0;
        #pragma unroll
        for (int w = 0; w < 12; w++) t += cw[tid][w];
        cnt_sh[tid] = t;
    }
    __syncthreads();

    if (tid == 0) {
        double msq[16], qm[16], Msq[4];
        #pragma unroll
        for (int k = 0; k < 16; k++) { msq[k] = 0.0; qm[k] = 0.0; }
        #pragma unroll
        for (int m = 0; m < 4; m++) Msq[m] = 0.0;
        #pragma unroll
        for (int w = 0; w < 12; w++) {
            const int m = (w < 8) ? 0 : (w == 8) ? 1 : (w == 9) ? 2 : 3;
            #pragma unroll
            for (int g = 0; g < 4; g++) {
                msq[m * 4 + g] += wr[w][g];
                qm [m * 4 + g] += wr[w][4 + g];
            }
            Msq[m] += wr[w][8];
        }

        double n[4], cpos = 0.0;
        #pragma unroll
        for (int g = 0; g < 4; g++) {
            n[g] = (double)cnt_sh[g];
            cpos += 0.5 * n[g] * (n[g] - 1.0);
        }
        const double Bv = (double)NB;
        const double cneg = 0.5 * Bv * (Bv - 1.0) - cpos;
        const double icp = 1.0 / cpos, icn = 1.0 / cneg;
        const double idm[4] = {1.0/1024.0, 1.0/64.0, 1.0/128.0, 1.0/256.0};

        double loss[4];
        #pragma unroll
        for (int m = 0; m < 4; m++) {
            double Spos = 0.0, Q = 0.0;
            #pragma unroll
            for (int g = 0; g < 4; g++) {
                Spos += n[g] * qm[m * 4 + g] - msq[m * 4 + g];
                Q    += qm[m * 4 + g];
            }
            Spos *= idm[m];
            const double Sall = (Bv * Q - Msq[m]) * idm[m];
            const double Sneg = Sall - Spos;
            loss[m] = Spos * icp - Sneg * icn;
        }
        const double latent = (loss[1] + loss[2] + loss[3]) * (1.0 / 3.0);
        out[0] = (float)(0.5 * latent + 0.5 * loss[0]);      // W = 0.5
    }
    for (int i = 1 + tid; i < out_size; i += 384) out[i] = 0.0f;
}

// ---------------------------------------------------------------------------
extern "C" void kernel_launch(void* const* d_in, const int* in_sizes, int n_in,
                              void* d_out, int out_size) {
    const float* rep = (const float*)d_in[0];
    const float* a0  = (const float*)d_in[1];
    const float* a1  = (const float*)d_in[2];
    const float* a2  = (const float*)d_in[3];
    const int*   nl  = (const int*)d_in[4];

    kA_partial<<<dim3(3, NCHUNK), 128>>>(rep, a0, a1, a2, nl);
    kB_reduce<<<dim3(3, KB_Y), 128>>>();
    kC_final<<<1, 384>>>(nl, (float*)d_out, out_size);
}

// round 8
// speedup vs baseline: 1.4718x; 1.0420x over previous
#include <cuda_runtime.h>
#include <cstdint>

// ---------------------------------------------------------------------------
// DisentanglementModule loss, closed form (TAU_POS == TAU_NEG => tau cancels):
//   loss_x = S_pos/c_pos - S_neg/c_neg
//   S_pos  = sum_g (n_g * q_g - ||m_g||^2) / d
//   S_all  = (B * Q - ||M||^2) / d ,  S_neg = S_all - S_pos
// Column-separable: per-column per-group sums (m) + sums-of-squares (q).
//
// Flattened column space: 384 float4 "slots", warp-aligned per matrix:
//   slots [0,256)    rep  (1024 cols)                 warps 0-7
//   slots [256,272)  act0 (64 cols); [272,288) pad    warp 8
//   slots [288,320)  act1 (128 cols)                  warp 9
//   slots [320,384)  act2 (256 cols)                  warps 10-11
// kA: grid (3, 256) streams features -> per-chunk per-group slot partials
// kB: grid 48, slot-major reduce over all 256 chunks -> ONE reduced plane
// kC: 1 block x 384 finalize (tiny reads).
// ---------------------------------------------------------------------------

#define NB      4096
#define NCHUNK  256
#define RPC     16                  // rows per chunk (NCHUNK*RPC == NB)
#define NSLOT   384
#define KB_BLK  48                  // kB blocks (8 slots each)
#define KB_PART 16                  // chunk-parts per slot in kB
#define KB_CPP  (NCHUNK / KB_PART)  // chunks per part = 16
#define FULL    0xFFFFFFFFu

// Scratch: every element rewritten each launch -> graph-replay safe.
__device__ __align__(16) float4 g_Spart[NCHUNK * 4 * NSLOT]; // 6.3MB col sums
__device__ float  g_Qpart[NCHUNK * 4 * NSLOT];               // 1.6MB col sumsq
__device__ __align__(16) float4 g_S2[4 * NSLOT];             // 24KB reduced
__device__ float  g_Q2[4 * NSLOT];                           // 6KB reduced

#define F4Z make_float4(0.f, 0.f, 0.f, 0.f)
__device__ __forceinline__ void f4add(float4& a, const float4 b) {
    a.x += b.x; a.y += b.y; a.z += b.z; a.w += b.w;
}

// int64-vs-int32 detection: values in [0,3]; if int64 (LE), odd words are 0
// and even words <= 3. Vote over first 1024 pairs via __syncthreads_count.
__device__ __forceinline__ int detect_int64(const int* __restrict__ nl, int tid, int nthr) {
    int bad = 0;
    for (int i = tid; i < 1024; i += nthr) {
        const int lo = nl[2 * i], hi = nl[2 * i + 1];
        if (hi != 0 || (unsigned)lo > 3u) bad = 1;
    }
    return __syncthreads_count(bad) == 0;
}

// ---------------------------------------------------------------------------
// kA: streaming pass. grid=(3, NCHUNK), 128 threads; thread = one slot.
// ---------------------------------------------------------------------------
#define ACC8(S, T, x) do {                                   \
    S.x += x.x; S.y += x.y; S.z += x.z; S.w += x.w;          \
    T.x = fmaf(x.x, x.x, T.x); T.y = fmaf(x.y, x.y, T.y);    \
    T.z = fmaf(x.z, x.z, T.z); T.w = fmaf(x.w, x.w, T.w); } while (0)

__global__ __launch_bounds__(128) void kA_partial(
    const float* __restrict__ rep, const float* __restrict__ a0,
    const float* __restrict__ a1,  const float* __restrict__ a2,
    const int* __restrict__ nl)
{
    const int tid   = threadIdx.x;
    const int slot  = blockIdx.x * 128 + tid;
    const int chunk = blockIdx.y;
    const int row0  = chunk * RPC;

    const int is64 = detect_int64(nl, tid, 128);     // barrier inside
    __shared__ int gsh[RPC];
    if (tid < RPC)
        gsh[tid] = (is64 ? nl[2 * (row0 + tid)] : nl[row0 + tid]) & 3;
    __syncthreads();

    // Slot -> (src, ld, col). act2 owns [320,384) fully; pad = [272,288).
    const float* src; int ld, col, active = 1;
    if (slot < 256)      { src = rep; ld = 1024; col = slot * 4; }
    else if (slot < 272) { src = a0;  ld = 512;  col = (slot - 256) * 4; }
    else if (slot < 288) { src = a0;  ld = 512;  col = 0; active = 0; }  // pad
    else if (slot < 320) { src = a1;  ld = 512;  col = (slot - 288) * 4; }
    else                 { src = a2;  ld = 512;  col = (slot - 320) * 4; }

    float4 sA = F4Z, sB = F4Z, sC = F4Z, sD = F4Z;
    float4 tA = F4Z, tB = F4Z, tC = F4Z, tD = F4Z;

    if (active) {
        const float* p = src + (size_t)row0 * ld + col;
        #pragma unroll 1
        for (int r = 0; r < RPC; r += 8) {
            float4 v[8]; int gg[8];
            #pragma unroll
            for (int u = 0; u < 8; u++) {                       // batch for MLP
                v[u]  = *reinterpret_cast<const float4*>(p + (size_t)(r + u) * ld);
                gg[u] = gsh[r + u];
            }
            #pragma unroll
            for (int u = 0; u < 8; u++) {
                const float4 x = v[u];
                const int g = gg[u];                            // warp-uniform
                if      (g == 0) ACC8(sA, tA, x);
                else if (g == 1) ACC8(sB, tB, x);
                else if (g == 2) ACC8(sC, tC, x);
                else             ACC8(sD, tD, x);
            }
        }
    }

    // Store partials (idle slots store zeros: scratch fully rewritten).
    const int base = (chunk * 4) * NSLOT + slot;
    g_Spart[base + 0 * NSLOT] = sA;
    g_Spart[base + 1 * NSLOT] = sB;
    g_Spart[base + 2 * NSLOT] = sC;
    g_Spart[base + 3 * NSLOT] = sD;
    g_Qpart[base + 0 * NSLOT] = tA.x + tA.y + tA.z + tA.w;
    g_Qpart[base + 1 * NSLOT] = tB.x + tB.y + tB.z + tB.w;
    g_Qpart[base + 2 * NSLOT] = tC.x + tC.y + tC.z + tC.w;
    g_Qpart[base + 3 * NSLOT] = tD.x + tD.y + tD.z + tD.w;
}

// ---------------------------------------------------------------------------
// kB: slot-major chunk reduction -> single fully reduced plane.
// grid = KB_BLK(48), 128 threads. Block owns 8 slots; thread (t&7)=slot-local,
// (t>>3)=part handles KB_CPP chunks; shared combine over 16 parts.
// ---------------------------------------------------------------------------
__global__ __launch_bounds__(128) void kB_reduce() {
    const int tid  = threadIdx.x;
    const int sl   = tid & 7;            // slot within block
    const int part = tid >> 3;           // 0..15
    const int slot = blockIdx.x * 8 + sl;

    float4 s[4] = {F4Z, F4Z, F4Z, F4Z};
    float  q[4] = {0.f, 0.f, 0.f, 0.f};
    const int c0 = part * KB_CPP;
    #pragma unroll 4
    for (int c = 0; c < KB_CPP; c++) {
        const int b = ((c0 + c) * 4) * NSLOT + slot;
        f4add(s[0], g_Spart[b + 0 * NSLOT]);
        f4add(s[1], g_Spart[b + 1 * NSLOT]);
        f4add(s[2], g_Spart[b + 2 * NSLOT]);
        f4add(s[3], g_Spart[b + 3 * NSLOT]);
        q[0] += g_Qpart[b + 0 * NSLOT];
        q[1] += g_Qpart[b + 1 * NSLOT];
        q[2] += g_Qpart[b + 2 * NSLOT];
        q[3] += g_Qpart[b + 3 * NSLOT];
    }

    __shared__ float4 shS[128][4];
    __shared__ float  shQ[128][4];
    #pragma unroll
    for (int g = 0; g < 4; g++) { shS[tid][g] = s[g]; shQ[tid][g] = q[g]; }
    __syncthreads();

    // 32 combiner threads: (slot-local, group) pairs; fixed-order over parts.
    if (tid < 32) {
        const int csl = tid & 7, g = tid >> 3;
        float4 S = F4Z; float Q = 0.f;
        #pragma unroll
        for (int p = 0; p < KB_PART; p++) {
            f4add(S, shS[p * 8 + csl][g]);
            Q += shQ[p * 8 + csl][g];
        }
        const int oslot = blockIdx.x * 8 + csl;
        g_S2[g * NSLOT + oslot] = S;
        g_Q2[g * NSLOT + oslot] = Q;
    }
}

// ---------------------------------------------------------------------------
// kC: finalize. 1 block x 384 (12 warps); thread = slot; warp-uniform matrix.
// Warps 0-7 -> m0(rep,1024); warp 8 -> m1(act0,64); warp 9 -> m2(act1,128);
// warps 10-11 -> m3(act2,256). Pad slots carry zeros.
// ---------------------------------------------------------------------------
__global__ __launch_bounds__(384) void kC_final(
    const int* __restrict__ nl, float* __restrict__ out, int out_size)
{
    const int tid = threadIdx.x, lane = tid & 31, warp = tid >> 5;

    float4 S[4]; float q[4];
    #pragma unroll
    for (int g = 0; g < 4; g++) {
        S[g] = g_S2[g * NSLOT + tid];
        q[g] = g_Q2[g * NSLOT + tid];
    }

    // 9 per-slot doubles: msq_g (4), q_g (4), Msq (1).
    double v[9];
    float4 st = F4Z;
    #pragma unroll
    for (int g = 0; g < 4; g++) {
        v[g] = (double)S[g].x * S[g].x + (double)S[g].y * S[g].y
             + (double)S[g].z * S[g].z + (double)S[g].w * S[g].w;
        v[4 + g] = (double)q[g];
        f4add(st, S[g]);
    }
    v[8] = (double)st.x * st.x + (double)st.y * st.y
         + (double)st.z * st.z + (double)st.w * st.w;

    __shared__ double wr[12][9];
    #pragma unroll
    for (int k = 0; k < 9; k++) {
        double x = v[k];
        #pragma unroll
        for (int off = 16; off > 0; off >>= 1) x += __shfl_down_sync(FULL, x, off);
        if (lane == 0) wr[warp][k] = x;
    }

    // Group counts (detect has a barrier inside, ordering wr before reads).
    const int is64 = detect_int64(nl, tid, 384);
    int c[4] = {0, 0, 0, 0};
    for (int i = tid; i < NB; i += 384) {
        const int g = (is64 ? nl[2 * i] : nl[i]) & 3;
        c[g]++;
    }
    __shared__ int cw[4][12];
    __shared__ int cnt_sh[4];
    #pragma unroll
    for (int g = 0; g < 4; g++) {
        int x = c[g];
        #pragma unroll
        for (int off = 16; off > 0; off >>= 1) x += __shfl_down_sync(FULL, x, off);
        if (lane == 0) cw[g][warp] = x;
    }
    __syncthreads();
    if (tid < 4) {
        int t = 0;
        #pragma unroll
        for (int w = 0; w < 12; w++) t += cw[tid][w];
        cnt_sh[tid] = t;
    }
    __syncthreads();

    if (tid == 0) {
        double msq[16], qm[16], Msq[4];
        #pragma unroll
        for (int k = 0; k < 16; k++) { msq[k] = 0.0; qm[k] = 0.0; }
        #pragma unroll
        for (int m = 0; m < 4; m++) Msq[m] = 0.0;
        #pragma unroll
        for (int w = 0; w < 12; w++) {
            const int m = (w < 8) ? 0 : (w == 8) ? 1 : (w == 9) ? 2 : 3;
            #pragma unroll
            for (int g = 0; g < 4; g++) {
                msq[m * 4 + g] += wr[w][g];
                qm [m * 4 + g] += wr[w][4 + g];
            }
            Msq[m] += wr[w][8];
        }

        double n[4], cpos = 0.0;
        #pragma unroll
        for (int g = 0; g < 4; g++) {
            n[g] = (double)cnt_sh[g];
            cpos += 0.5 * n[g] * (n[g] - 1.0);
        }
        const double Bv = (double)NB;
        const double cneg = 0.5 * Bv * (Bv - 1.0) - cpos;
        const double icp = 1.0 / cpos, icn = 1.0 / cneg;
        const double idm[4] = {1.0/1024.0, 1.0/64.0, 1.0/128.0, 1.0/256.0};

        double loss[4];
        #pragma unroll
        for (int m = 0; m < 4; m++) {
            double Spos = 0.0, Q = 0.0;
            #pragma unroll
            for (int g = 0; g < 4; g++) {
                Spos += n[g] * qm[m * 4 + g] - msq[m * 4 + g];
                Q    += qm[m * 4 + g];
            }
            Spos *= idm[m];
            const double Sall = (Bv * Q - Msq[m]) * idm[m];
            const double Sneg = Sall - Spos;
            loss[m] = Spos * icp - Sneg * icn;
        }
        const double latent = (loss[1] + loss[2] + loss[3]) * (1.0 / 3.0);
        out[0] = (float)(0.5 * latent + 0.5 * loss[0]);      // W = 0.5
    }
    for (int i = 1 + tid; i < out_size; i += 384) out[i] = 0.0f;
}

// ---------------------------------------------------------------------------
extern "C" void kernel_launch(void* const* d_in, const int* in_sizes, int n_in,
                              void* d_out, int out_size) {
    const float* rep = (const float*)d_in[0];
    const float* a0  = (const float*)d_in[1];
    const float* a1  = (const float*)d_in[2];
    const float* a2  = (const float*)d_in[3];
    const int*   nl  = (const int*)d_in[4];

    kA_partial<<<dim3(3, NCHUNK), 128>>>(rep, a0, a1, a2, nl);
    kB_reduce<<<KB_BLK, 128>>>();
    kC_final<<<1, 384>>>(nl, (float*)d_out, out_size);
}

// round 9
// speedup vs baseline: 1.8949x; 1.2875x over previous
#include <cuda_runtime.h>
#include <cstdint>

// ---------------------------------------------------------------------------
// DisentanglementModule loss, closed form (TAU_POS == TAU_NEG => tau cancels):
//   loss_x = S_pos/c_pos - S_neg/c_neg
//   S_pos  = sum_g (n_g * q_g - ||m_g||^2) / d
//   S_all  = (B * Q - ||M||^2) / d ,  S_neg = S_all - S_pos
// Column-separable: per-column per-group sums (m) + sums-of-squares (q).
//
// Flattened column space: 384 float4 "slots", warp-aligned per matrix:
//   slots [0,256)    rep  (1024 cols)                 warps 0-7
//   slots [256,272)  act0 (64 cols); [272,288) pad    warp 8
//   slots [288,320)  act1 (128 cols)                  warp 9
//   slots [320,384)  act2 (256 cols)                  warps 10-11
//
// kA: grid (3,128), cp.async double-buffered streaming (register-free loads
//     -> deep MLP -> DRAM saturation) -> per-chunk per-group slot partials.
// kB: grid 48, slot-major reduce over 128 chunks -> ONE reduced plane (L2 hits)
// kC: 1 block x 384 finalize (tiny reads).
// ---------------------------------------------------------------------------

#define NB      4096
#define NCHUNK  128
#define RPC     32                  // rows per chunk (NCHUNK*RPC == NB)
#define NSTG    4                   // stages per chunk (8 rows each)
#define NSLOT   384
#define KB_BLK  48                  // kB blocks (8 slots each)
#define KB_PART 16                  // chunk-parts per slot in kB
#define KB_CPP  (NCHUNK / KB_PART)  // chunks per part = 8
#define FULL    0xFFFFFFFFu

// Scratch: every element rewritten each launch -> graph-replay safe.
__device__ __align__(16) float4 g_Spart[NCHUNK * 4 * NSLOT]; // 3.1MB col sums
__device__ float  g_Qpart[NCHUNK * 4 * NSLOT];               // 786KB col sumsq
__device__ __align__(16) float4 g_S2[4 * NSLOT];             // 24KB reduced
__device__ float  g_Q2[4 * NSLOT];                           // 6KB reduced

#define F4Z make_float4(0.f, 0.f, 0.f, 0.f)
__device__ __forceinline__ void f4add(float4& a, const float4 b) {
    a.x += b.x; a.y += b.y; a.z += b.z; a.w += b.w;
}

#define CPASYNC16(sa, ga) \
    asm volatile("cp.async.cg.shared.global [%0], [%1], 16;" :: "r"(sa), "l"(ga))
#define CPCOMMIT()  asm volatile("cp.async.commit_group;" ::: "memory")
#define CPWAIT1()   asm volatile("cp.async.wait_group 1;" ::: "memory")
#define CPWAIT0()   asm volatile("cp.async.wait_group 0;" ::: "memory")

// int64-vs-int32 detection: values in [0,3]; if int64 (LE), odd words are 0
// and even words <= 3. Vote over first 1024 pairs via __syncthreads_count.
__device__ __forceinline__ int detect_int64(const int* __restrict__ nl, int tid, int nthr) {
    int bad = 0;
    for (int i = tid; i < 1024; i += nthr) {
        const int lo = nl[2 * i], hi = nl[2 * i + 1];
        if (hi != 0 || (unsigned)lo > 3u) bad = 1;
    }
    return __syncthreads_count(bad) == 0;
}

// ---------------------------------------------------------------------------
// kA: cp.async streaming pass. grid=(3, NCHUNK), 128 threads; thread = slot.
// Each thread stages its own 16B/row into shared (LDGSTS: no regs, deep MLP),
// consumes ONLY its own staged bytes -> no barriers in the pipeline loop.
// ---------------------------------------------------------------------------
#define ACC8(S, T, x) do {                                   \
    S.x += x.x; S.y += x.y; S.z += x.z; S.w += x.w;          \
    T.x = fmaf(x.x, x.x, T.x); T.y = fmaf(x.y, x.y, T.y);    \
    T.z = fmaf(x.z, x.z, T.z); T.w = fmaf(x.w, x.w, T.w); } while (0)

__global__ __launch_bounds__(128) void kA_partial(
    const float* __restrict__ rep, const float* __restrict__ a0,
    const float* __restrict__ a1,  const float* __restrict__ a2,
    const int* __restrict__ nl)
{
    __shared__ float4 buf[2][8][128];            // 32KB double buffer
    const int tid   = threadIdx.x;
    const int slot  = blockIdx.x * 128 + tid;
    const int chunk = blockIdx.y;
    const int row0  = chunk * RPC;

    const int is64 = detect_int64(nl, tid, 128); // barrier inside
    __shared__ int gsh[RPC];
    if (tid < RPC)
        gsh[tid] = (is64 ? nl[2 * (row0 + tid)] : nl[row0 + tid]) & 3;
    __syncthreads();

    // Slot -> (src, ld, col). act2 owns [320,384) fully; pad = [272,288).
    const float* src; int ld, col, active = 1;
    if (slot < 256)      { src = rep; ld = 1024; col = slot * 4; }
    else if (slot < 272) { src = a0;  ld = 512;  col = (slot - 256) * 4; }
    else if (slot < 288) { src = a0;  ld = 512;  col = 0; active = 0; }  // pad
    else if (slot < 320) { src = a1;  ld = 512;  col = (slot - 288) * 4; }
    else                 { src = a2;  ld = 512;  col = (slot - 320) * 4; }

    const float* p = src + (size_t)row0 * ld + col;
    const uint32_t sbase = (uint32_t)__cvta_generic_to_shared(&buf[0][0][tid]);
    // stage s (0/1), row r -> sbase + (s*8 + r) * 128 * 16

    float4 sA = F4Z, sB = F4Z, sC = F4Z, sD = F4Z;
    float4 tA = F4Z, tB = F4Z, tC = F4Z, tD = F4Z;

    // Prologue: stage 0 (rows 0..7).
    if (active) {
        #pragma unroll
        for (int r = 0; r < 8; r++)
            CPASYNC16(sbase + (0 * 8 + r) * 2048, p + (size_t)r * ld);
    }
    CPCOMMIT();

    #pragma unroll
    for (int k = 0; k < NSTG; k++) {
        if (k + 1 < NSTG) {
            if (active) {
                const int b1 = (k + 1) & 1;
                #pragma unroll
                for (int r = 0; r < 8; r++)
                    CPASYNC16(sbase + (b1 * 8 + r) * 2048,
                              p + (size_t)((k + 1) * 8 + r) * ld);
            }
            CPCOMMIT();
            CPWAIT1();                     // stage k landed, k+1 in flight
        } else {
            CPWAIT0();                     // last stage landed
        }
        if (active) {
            const int b = k & 1;
            #pragma unroll
            for (int r = 0; r < 8; r++) {
                const float4 x = buf[b][r][tid];
                const int g = gsh[k * 8 + r];            // warp-uniform
                if      (g == 0) ACC8(sA, tA, x);
                else if (g == 1) ACC8(sB, tB, x);
                else if (g == 2) ACC8(sC, tC, x);
                else             ACC8(sD, tD, x);
            }
        }
    }

    // Store partials (idle slots store zeros: scratch fully rewritten).
    const int base = (chunk * 4) * NSLOT + slot;
    g_Spart[base + 0 * NSLOT] = sA;
    g_Spart[base + 1 * NSLOT] = sB;
    g_Spart[base + 2 * NSLOT] = sC;
    g_Spart[base + 3 * NSLOT] = sD;
    g_Qpart[base + 0 * NSLOT] = tA.x + tA.y + tA.z + tA.w;
    g_Qpart[base + 1 * NSLOT] = tB.x + tB.y + tB.z + tB.w;
    g_Qpart[base + 2 * NSLOT] = tC.x + tC.y + tC.z + tC.w;
    g_Qpart[base + 3 * NSLOT] = tD.x + tD.y + tD.z + tD.w;
}

// ---------------------------------------------------------------------------
// kB: slot-major chunk reduction -> single fully reduced plane (L2 hits).
// grid = KB_BLK(48), 128 threads. Block owns 8 slots; thread (t&7)=slot-local,
// (t>>3)=part handles KB_CPP chunks; shared combine over 16 parts.
// ---------------------------------------------------------------------------
__global__ __launch_bounds__(128) void kB_reduce() {
    const int tid  = threadIdx.x;
    const int sl   = tid & 7;            // slot within block
    const int part = tid >> 3;           // 0..15
    const int slot = blockIdx.x * 8 + sl;

    float4 s[4] = {F4Z, F4Z, F4Z, F4Z};
    float  q[4] = {0.f, 0.f, 0.f, 0.f};
    const int c0 = part * KB_CPP;
    #pragma unroll
    for (int c = 0; c < KB_CPP; c++) {
        const int b = ((c0 + c) * 4) * NSLOT + slot;
        f4add(s[0], g_Spart[b + 0 * NSLOT]);
        f4add(s[1], g_Spart[b + 1 * NSLOT]);
        f4add(s[2], g_Spart[b + 2 * NSLOT]);
        f4add(s[3], g_Spart[b + 3 * NSLOT]);
        q[0] += g_Qpart[b + 0 * NSLOT];
        q[1] += g_Qpart[b + 1 * NSLOT];
        q[2] += g_Qpart[b + 2 * NSLOT];
        q[3] += g_Qpart[b + 3 * NSLOT];
    }

    __shared__ float4 shS[128][4];
    __shared__ float  shQ[128][4];
    #pragma unroll
    for (int g = 0; g < 4; g++) { shS[tid][g] = s[g]; shQ[tid][g] = q[g]; }
    __syncthreads();

    // 32 combiner threads: (slot-local, group) pairs; fixed-order over parts.
    if (tid < 32) {
        const int csl = tid & 7, g = tid >> 3;
        float4 S = F4Z; float Q = 0.f;
        #pragma unroll
        for (int p = 0; p < KB_PART; p++) {
            f4add(S, shS[p * 8 + csl][g]);
            Q += shQ[p * 8 + csl][g];
        }
        const int oslot = blockIdx.x * 8 + csl;
        g_S2[g * NSLOT + oslot] = S;
        g_Q2[g * NSLOT + oslot] = Q;
    }
}

// ---------------------------------------------------------------------------
// kC: finalize. 1 block x 384 (12 warps); thread = slot; warp-uniform matrix.
// Warps 0-7 -> m0(rep,1024); warp 8 -> m1(act0,64); warp 9 -> m2(act1,128);
// warps 10-11 -> m3(act2,256). Pad slots carry zeros.
// ---------------------------------------------------------------------------
__global__ __launch_bounds__(384) void kC_final(
    const int* __restrict__ nl, float* __restrict__ out, int out_size)
{
    const int tid = threadIdx.x, lane = tid & 31, warp = tid >> 5;

    float4 S[4]; float q[4];
    #pragma unroll
    for (int g = 0; g < 4; g++) {
        S[g] = g_S2[g * NSLOT + tid];
        q[g] = g_Q2[g * NSLOT + tid];
    }

    // 9 per-slot doubles: msq_g (4), q_g (4), Msq (1).
    double v[9];
    float4 st = F4Z;
    #pragma unroll
    for (int g = 0; g < 4; g++) {
        v[g] = (double)S[g].x * S[g].x + (double)S[g].y * S[g].y
             + (double)S[g].z * S[g].z + (double)S[g].w * S[g].w;
        v[4 + g] = (double)q[g];
        f4add(st, S[g]);
    }
    v[8] = (double)st.x * st.x + (double)st.y * st.y
         + (double)st.z * st.z + (double)st.w * st.w;

    __shared__ double wr[12][9];
    #pragma unroll
    for (int k = 0; k < 9; k++) {
        double x = v[k];
        #pragma unroll
        for (int off = 16; off > 0; off >>= 1) x += __shfl_down_sync(FULL, x, off);
        if (lane == 0) wr[warp][k] = x;
    }

    // Group counts (detect has a barrier inside, ordering wr before reads).
    const int is64 = detect_int64(nl, tid, 384);
    int c[4] = {0, 0, 0, 0};
    for (int i = tid; i < NB; i += 384) {
        const int g = (is64 ? nl[2 * i] : nl[i]) & 3;
        c[g]++;
    }
    __shared__ int cw[4][12];
    __shared__ int cnt_sh[4];
    #pragma unroll
    for (int g = 0; g < 4; g++) {
        int x = c[g];
        #pragma unroll
        for (int off = 16; off > 0; off >>= 1) x += __shfl_down_sync(FULL, x, off);
        if (lane == 0) cw[g][warp] = x;
    }
    __syncthreads();
    if (tid < 4) {
        int t = 0;
        #pragma unroll
        for (int w = 0; w < 12; w++) t += cw[tid][w];
        cnt_sh[tid] = t;
    }
    __syncthreads();

    if (tid == 0) {
        double msq[16], qm[16], Msq[4];
        #pragma unroll
        for (int k = 0; k < 16; k++) { msq[k] = 0.0; qm[k] = 0.0; }
        #pragma unroll
        for (int m = 0; m < 4; m++) Msq[m] = 0.0;
        #pragma unroll
        for (int w = 0; w < 12; w++) {
            const int m = (w < 8) ? 0 : (w == 8) ? 1 : (w == 9) ? 2 : 3;
            #pragma unroll
            for (int g = 0; g < 4; g++) {
                msq[m * 4 + g] += wr[w][g];
                qm [m * 4 + g] += wr[w][4 + g];
            }
            Msq[m] += wr[w][8];
        }

        double n[4], cpos = 0.0;
        #pragma unroll
        for (int g = 0; g < 4; g++) {
            n[g] = (double)cnt_sh[g];
            cpos += 0.5 * n[g] * (n[g] - 1.0);
        }
        const double Bv = (double)NB;
        const double cneg = 0.5 * Bv * (Bv - 1.0) - cpos;
        const double icp = 1.0 / cpos, icn = 1.0 / cneg;
        const double idm[4] = {1.0/1024.0, 1.0/64.0, 1.0/128.0, 1.0/256.0};

        double loss[4];
        #pragma unroll
        for (int m = 0; m < 4; m++) {
            double Spos = 0.0, Q = 0.0;
            #pragma unroll
            for (int g = 0; g < 4; g++) {
                Spos += n[g] * qm[m * 4 + g] - msq[m * 4 + g];
                Q    += qm[m * 4 + g];
            }
            Spos *= idm[m];
            const double Sall = (Bv * Q - Msq[m]) * idm[m];
            const double Sneg = Sall - Spos;
            loss[m] = Spos * icp - Sneg * icn;
        }
        const double latent = (loss[1] + loss[2] + loss[3]) * (1.0 / 3.0);
        out[0] = (float)(0.5 * latent + 0.5 * loss[0]);      // W = 0.5
    }
    for (int i = 1 + tid; i < out_size; i += 384) out[i] = 0.0f;
}

// ---------------------------------------------------------------------------
extern "C" void kernel_launch(void* const* d_in, const int* in_sizes, int n_in,
                              void* d_out, int out_size) {
    const float* rep = (const float*)d_in[0];
    const float* a0  = (const float*)d_in[1];
    const float* a1  = (const float*)d_in[2];
    const float* a2  = (const float*)d_in[3];
    const int*   nl  = (const int*)d_in[4];

    kA_partial<<<dim3(3, NCHUNK), 128>>>(rep, a0, a1, a2, nl);
    kB_reduce<<<KB_BLK, 128>>>();
    kC_final<<<1, 384>>>(nl, (float*)d_out, out_size);
}